// round 8
// baseline (speedup 1.0000x reference)
#include <cuda_runtime.h>
#include <math.h>

// Problem constants
#define B_   2
#define S_   2048
#define DM_  1024
#define H_   16
#define DK_  64
#define BS_TOK 4096                // B*S
#define NBH  32                    // B*H

#define N_ACT  4194304             // BS_TOK * DM_
#define N_W    1048576
#define N_BIAS 1024
#define N_ATTN 134217728           // NBH * S * S

// Scratch (module-load allocated; legal)
__device__ float g_Qp[N_ACT];          // [BS, D] plain Q projection
__device__ float g_Kp[N_ACT];          // [BS, D] plain K projection
__device__ float g_Vp[N_ACT];          // [BS, D] plain V projection
__device__ float g_ctx[N_ACT];         // [BS, D] merged context
__device__ float g_attn_scratch[N_ATTN];
__device__ float g_out_scratch [N_ACT];

// ===========================================================================
// Projection GEMM (NN): C[m][n] = sum_k A[m][k]*W[k][n] + bias[n]
// M=4096, N=1024, K=1024. Tile 128x64x16, 256 threads, 8x4 per thread.
// ===========================================================================
__global__ __launch_bounds__(256) void gemm_proj(const float* __restrict__ A,
                                                 const float* __restrict__ W,
                                                 const float* __restrict__ bias,
                                                 float* __restrict__ C) {
    __shared__ float As[16][128];   // As[k][m]
    __shared__ float Bs[16][64];    // Bs[k][n]
    const int t  = threadIdx.x;
    const int tx = t & 15;          // n-group: cols tx*4 .. tx*4+3
    const int ty = t >> 4;          // m-group: rows ty*8 .. ty*8+7
    const int m0 = blockIdx.y * 128;
    const int n0 = blockIdx.x * 64;

    float acc[8][4];
#pragma unroll
    for (int i = 0; i < 8; i++)
#pragma unroll
        for (int j = 0; j < 4; j++) acc[i][j] = 0.f;

    for (int k0 = 0; k0 < DM_; k0 += 16) {
        // A tile: 128 rows x 16 k  (512 float4, 2 per thread), stored transposed
#pragma unroll
        for (int rep = 0; rep < 2; rep++) {
            const int lin = t + rep * 256;      // [0,512)
            const int row = lin >> 2;           // [0,128)
            const int kc  = (lin & 3) << 2;     // {0,4,8,12}
            const float4 v4 = *(const float4*)(A + (size_t)(m0 + row) * DM_ + k0 + kc);
            As[kc + 0][row] = v4.x;  As[kc + 1][row] = v4.y;
            As[kc + 2][row] = v4.z;  As[kc + 3][row] = v4.w;
        }
        // W tile: 16 k x 64 n (256 float4, 1 per thread)
        {
            const int kk = t >> 4;              // [0,16)
            const int nc = (t & 15) << 2;       // [0,64)
            *(float4*)&Bs[kk][nc] =
                *(const float4*)(W + (size_t)(k0 + kk) * DM_ + n0 + nc);
        }
        __syncthreads();
#pragma unroll
        for (int kk = 0; kk < 16; kk++) {
            float a[8], b[4];
#pragma unroll
            for (int i = 0; i < 8; i++) a[i] = As[kk][ty * 8 + i];
#pragma unroll
            for (int j = 0; j < 4; j++) b[j] = Bs[kk][tx * 4 + j];
#pragma unroll
            for (int i = 0; i < 8; i++)
#pragma unroll
                for (int j = 0; j < 4; j++) acc[i][j] += a[i] * b[j];
        }
        __syncthreads();
    }

#pragma unroll
    for (int i = 0; i < 8; i++) {
        const int m = m0 + ty * 8 + i;
#pragma unroll
        for (int j = 0; j < 4; j++) {
            const int n = n0 + tx * 4 + j;
            C[(size_t)m * DM_ + n] = acc[i][j] + bias[n];
        }
    }
}

// ===========================================================================
// Scores GEMM (NT): per z=(b*16+h):
//   attn_z[q][kk] = (1/8) * sum_d Qh[q][d] * Kh[kk][d]
// where Qh row q = g_Qp[b*2048+q][h*64 .. h*64+63]  (row stride DM_)
// Tile 128x64x16 over the [2048 x 2048] output.
// ===========================================================================
__global__ __launch_bounds__(256) void gemm_scores(float* __restrict__ attn) {
    const int z = blockIdx.z;
    const int b = z >> 4, h = z & 15;
    const float* Aq = g_Qp + (size_t)b * S_ * DM_ + h * DK_;  // [2048 x 64], lda=DM_
    const float* Bk = g_Kp + (size_t)b * S_ * DM_ + h * DK_;  // [2048 x 64], ldb=DM_
    float* Cc = attn + (size_t)z * S_ * S_;

    __shared__ float As[16][128];   // As[k][q-row]
    __shared__ float Bs[16][64];    // Bs[k][k-row(col of C)]
    const int t  = threadIdx.x;
    const int tx = t & 15;
    const int ty = t >> 4;
    const int m0 = blockIdx.y * 128;
    const int n0 = blockIdx.x * 64;

    float acc[8][4];
#pragma unroll
    for (int i = 0; i < 8; i++)
#pragma unroll
        for (int j = 0; j < 4; j++) acc[i][j] = 0.f;

#pragma unroll
    for (int k0 = 0; k0 < DK_; k0 += 16) {
        // A tile (Q rows): 128 x 16, transposed store
#pragma unroll
        for (int rep = 0; rep < 2; rep++) {
            const int lin = t + rep * 256;
            const int row = lin >> 2;
            const int kc  = (lin & 3) << 2;
            const float4 v4 = *(const float4*)(Aq + (size_t)(m0 + row) * DM_ + k0 + kc);
            As[kc + 0][row] = v4.x;  As[kc + 1][row] = v4.y;
            As[kc + 2][row] = v4.z;  As[kc + 3][row] = v4.w;
        }
        // B tile (K rows, transposed in smem): Bs[kk][c] = K[n0+c][k0+kk]
        // 64 rows x 4 float4 = 256 float4, 1 per thread
        {
            const int c   = t >> 2;             // [0,64)
            const int kc4 = (t & 3) << 2;       // {0,4,8,12}
            const float4 v4 = *(const float4*)(Bk + (size_t)(n0 + c) * DM_ + k0 + kc4);
            Bs[kc4 + 0][c] = v4.x;  Bs[kc4 + 1][c] = v4.y;
            Bs[kc4 + 2][c] = v4.z;  Bs[kc4 + 3][c] = v4.w;
        }
        __syncthreads();
#pragma unroll
        for (int kk = 0; kk < 16; kk++) {
            float a[8], b[4];
#pragma unroll
            for (int i = 0; i < 8; i++) a[i] = As[kk][ty * 8 + i];
#pragma unroll
            for (int j = 0; j < 4; j++) b[j] = Bs[kk][tx * 4 + j];
#pragma unroll
            for (int i = 0; i < 8; i++)
#pragma unroll
                for (int j = 0; j < 4; j++) acc[i][j] += a[i] * b[j];
        }
        __syncthreads();
    }

#pragma unroll
    for (int i = 0; i < 8; i++) {
        const int m = m0 + ty * 8 + i;
#pragma unroll
        for (int j = 0; j < 4; j++) {
            const int n = n0 + tx * 4 + j;
            Cc[(size_t)m * S_ + n] = acc[i][j] * 0.125f;   // 1/sqrt(64)
        }
    }
}

// ===========================================================================
// Row softmax over 2048, in place. One block (256 thr) per row; thread t owns
// the contiguous chunk [t*8, t*8+8).
// ===========================================================================
__global__ __launch_bounds__(256) void softmax_kernel(float* __restrict__ attn) {
    float* p = attn + (size_t)blockIdx.x * S_;
    const int t = threadIdx.x;
    __shared__ float red[256];

    float x[8];
    float mx = -INFINITY;
#pragma unroll
    for (int i = 0; i < 8; i++) {
        x[i] = p[t * 8 + i];
        mx = fmaxf(mx, x[i]);
    }
    red[t] = mx;
    __syncthreads();
    for (int o = 128; o > 0; o >>= 1) {
        if (t < o) red[t] = fmaxf(red[t], red[t + o]);
        __syncthreads();
    }
    mx = red[0];
    __syncthreads();

    float sm = 0.f;
#pragma unroll
    for (int i = 0; i < 8; i++) {
        x[i] = expf(x[i] - mx);
        sm += x[i];
    }
    red[t] = sm;
    __syncthreads();
    for (int o = 128; o > 0; o >>= 1) {
        if (t < o) red[t] += red[t + o];
        __syncthreads();
    }
    const float inv = 1.0f / red[0];
#pragma unroll
    for (int i = 0; i < 8; i++) p[t * 8 + i] = x[i] * inv;
}

// ===========================================================================
// Context GEMM (NN): per z=(b*16+h):
//   ctx[b, s, h*64+c] = sum_k attn_z[s][k] * Vh[k][c]
// Vh row k = g_Vp[b*2048+k][h*64 .. +63] (ldb=DM_). Output col slice of g_ctx.
// Tile 128x64x16 (single n-tile since Dk=64).
// ===========================================================================
__global__ __launch_bounds__(256) void gemm_ctx(const float* __restrict__ attn) {
    const int z = blockIdx.z;
    const int b = z >> 4, h = z & 15;
    const float* Aa = attn + (size_t)z * S_ * S_;              // [2048x2048], lda=S_
    const float* Bv = g_Vp + (size_t)b * S_ * DM_ + h * DK_;   // [2048x64],  ldb=DM_
    float*       Cc = g_ctx + (size_t)b * S_ * DM_ + h * DK_;  // [2048x64],  ldc=DM_

    __shared__ float As[16][128];
    __shared__ float Bs[16][64];
    const int t  = threadIdx.x;
    const int tx = t & 15;
    const int ty = t >> 4;
    const int m0 = blockIdx.y * 128;

    float acc[8][4];
#pragma unroll
    for (int i = 0; i < 8; i++)
#pragma unroll
        for (int j = 0; j < 4; j++) acc[i][j] = 0.f;

    for (int k0 = 0; k0 < S_; k0 += 16) {
        // A tile: attn rows, transposed store
#pragma unroll
        for (int rep = 0; rep < 2; rep++) {
            const int lin = t + rep * 256;
            const int row = lin >> 2;
            const int kc  = (lin & 3) << 2;
            const float4 v4 = *(const float4*)(Aa + (size_t)(m0 + row) * S_ + k0 + kc);
            As[kc + 0][row] = v4.x;  As[kc + 1][row] = v4.y;
            As[kc + 2][row] = v4.z;  As[kc + 3][row] = v4.w;
        }
        // B tile (NN): Bs[kk][c] = V[k0+kk][c]
        {
            const int kk = t >> 4;              // [0,16)
            const int nc = (t & 15) << 2;       // [0,64)
            *(float4*)&Bs[kk][nc] =
                *(const float4*)(Bv + (size_t)(k0 + kk) * DM_ + nc);
        }
        __syncthreads();
#pragma unroll
        for (int kk = 0; kk < 16; kk++) {
            float a[8], b[4];
#pragma unroll
            for (int i = 0; i < 8; i++) a[i] = As[kk][ty * 8 + i];
#pragma unroll
            for (int j = 0; j < 4; j++) b[j] = Bs[kk][tx * 4 + j];
#pragma unroll
            for (int i = 0; i < 8; i++)
#pragma unroll
                for (int j = 0; j < 4; j++) acc[i][j] += a[i] * b[j];
        }
        __syncthreads();
    }

#pragma unroll
    for (int i = 0; i < 8; i++) {
        const int m = m0 + ty * 8 + i;
#pragma unroll
        for (int j = 0; j < 4; j++) {
            Cc[(size_t)m * DM_ + tx * 4 + j] = acc[i][j];
        }
    }
}

// ===========================================================================
// Launch. Inputs: signature order (proven by R4 bit-identity with R1).
// Outputs: output-first in d_out (proven by R7's rel_err flip to ~1.0000).
// ===========================================================================
extern "C" void kernel_launch(void* const* d_in, const int* in_sizes, int n_in,
                              void* d_out, int out_size) {
    const float* q  = (const float*)d_in[0];
    const float* k  = (const float*)d_in[1];
    const float* v  = (const float*)d_in[2];
    const float* Wq = (const float*)d_in[3];
    const float* bq = (const float*)d_in[4];
    const float* Wk = (const float*)d_in[5];
    const float* bk = (const float*)d_in[6];
    const float* Wv = (const float*)d_in[7];
    const float* bv = (const float*)d_in[8];
    const float* Wo = (const float*)d_in[9];
    const float* bo = (const float*)d_in[10];

    float* out;
    float* attn;
    if (out_size == N_ACT) {                    // only output in d_out
        float* sa; cudaGetSymbolAddress((void**)&sa, g_attn_scratch);
        out = (float*)d_out; attn = sa;
    } else if (out_size == N_ATTN) {            // only attn in d_out
        float* so; cudaGetSymbolAddress((void**)&so, g_out_scratch);
        attn = (float*)d_out; out = so;
    } else {                                    // both: output first, then attn
        out  = (float*)d_out;
        attn = (float*)d_out + N_ACT;
    }

    float* Qp;  cudaGetSymbolAddress((void**)&Qp,  g_Qp);
    float* Kp;  cudaGetSymbolAddress((void**)&Kp,  g_Kp);
    float* Vp;  cudaGetSymbolAddress((void**)&Vp,  g_Vp);
    float* Ctx; cudaGetSymbolAddress((void**)&Ctx, g_ctx);

    dim3 blk(256);
    dim3 gproj(DM_ / 64, BS_TOK / 128);         // (16, 32)

    gemm_proj<<<gproj, blk>>>(q, Wq, bq, Qp);
    gemm_proj<<<gproj, blk>>>(k, Wk, bk, Kp);
    gemm_proj<<<gproj, blk>>>(v, Wv, bv, Vp);

    dim3 gsc(S_ / 64, S_ / 128, NBH);           // (32, 16, 32)
    gemm_scores<<<gsc, blk>>>(attn);

    softmax_kernel<<<(unsigned)(NBH * S_), blk>>>(attn);   // 65536 rows

    dim3 gctx(1, S_ / 128, NBH);                // (1, 16, 32)
    gemm_ctx<<<gctx, blk>>>(attn);

    gemm_proj<<<gproj, blk>>>(Ctx, Wo, bo, out);
}

// round 12
// speedup vs baseline: 2.2068x; 2.2068x over previous
#include <cuda_runtime.h>
#include <math.h>
#include <stdint.h>

// Problem constants
#define B_   2
#define S_   2048
#define DM_  1024
#define H_   16
#define DK_  64
#define BS_TOK 4096                // B*S
#define NBH  32                    // B*H

#define N_ACT  4194304             // BS_TOK * DM_
#define N_ATTN 134217728           // NBH * S * S

// Scratch (module-load allocated; legal)
__device__ float g_Qp[N_ACT];          // [BS, D] plain Q projection
__device__ float g_Kp[N_ACT];          // [BS, D] plain K projection
__device__ float g_Vp[N_ACT];          // [BS, D] plain V projection
__device__ float g_ctx[N_ACT];         // [BS, D] merged context
__device__ float g_attn_scratch[N_ATTN];
__device__ float g_out_scratch [N_ACT];

// ---------------------------------------------------------------------------
// tf32 helpers
// ---------------------------------------------------------------------------
__device__ __forceinline__ uint32_t f2tf32(float x) {
    uint32_t r;
    asm("cvt.rna.tf32.f32 %0, %1;" : "=r"(r) : "f"(x));
    return r;
}

__device__ __forceinline__ void mma_tf32(float& c0, float& c1, float& c2, float& c3,
                                         uint32_t a0, uint32_t a1, uint32_t a2, uint32_t a3,
                                         uint32_t b0, uint32_t b1) {
    asm("mma.sync.aligned.m16n8k8.row.col.f32.tf32.tf32.f32 "
        "{%0,%1,%2,%3}, {%4,%5,%6,%7}, {%8,%9}, {%0,%1,%2,%3};"
        : "+f"(c0), "+f"(c1), "+f"(c2), "+f"(c3)
        : "r"(a0), "r"(a1), "r"(a2), "r"(a3), "r"(b0), "r"(b1));
}

// ---------------------------------------------------------------------------
// Generic tf32 GEMM body: block tile 128(M) x 64(N) x 16(K), 256 threads.
// 8 warps arranged 4(M) x 2(N); warp tile 32x32 = 2 m-atoms x 4 n-atoms.
// Smem: As[m][k] stride 20, Bs[n][k] stride 20 (both tf32-rounded).
//   A-fragment (m16n8k8): a0=(g,t4) a1=(g+8,t4) a2=(g,t4+4) a3=(g+8,t4+4)
//   B-fragment:           b0=(k=t4,n=g) b1=(k=t4+4,n=g)
//   C-fragment:           c0=(g,2t4) c1=(g,2t4+1) c2/c3 at row+8
// TRANSB=true: gmem B is [K][N] row-major (weights, V) -> transposed smem fill.
// TRANSB=false: gmem B is [N][K] row-major (K-proj rows for NT scores GEMM).
// ---------------------------------------------------------------------------
#define AS_STRIDE 20
#define BS_STRIDE 20

template <bool TRANSB>
__device__ __forceinline__ void gemm_tile_tf32(
    const float* __restrict__ A, int lda,
    const float* __restrict__ B, int ldb,
    int K, int m0, int n0,
    uint32_t* As, uint32_t* Bs,
    float acc[2][4][4])
{
    const int t    = threadIdx.x;
    const int lane = t & 31;
    const int wid  = t >> 5;
    const int warp_m = (wid & 3) * 32;
    const int warp_n = (wid >> 2) * 32;
    const int g  = lane >> 2;
    const int t4 = lane & 3;

    for (int k0 = 0; k0 < K; k0 += 16) {
        // ---- fill As: 128 x 16 ----
#pragma unroll
        for (int rep = 0; rep < 2; rep++) {
            const int lin = t + rep * 256;       // [0,512)
            const int m   = lin >> 2;            // [0,128)
            const int k4  = (lin & 3) << 2;      // {0,4,8,12}
            const float4 v = *(const float4*)(A + (size_t)(m0 + m) * lda + k0 + k4);
            uint4 u;
            u.x = f2tf32(v.x); u.y = f2tf32(v.y);
            u.z = f2tf32(v.z); u.w = f2tf32(v.w);
            *(uint4*)&As[m * AS_STRIDE + k4] = u;
        }
        // ---- fill Bs: 64(n) x 16(k) ----
        if (TRANSB) {
            const int kk = t >> 4;               // [0,16)
            const int n4 = (t & 15) << 2;        // [0,64)
            const float4 v = *(const float4*)(B + (size_t)(k0 + kk) * ldb + n0 + n4);
            Bs[(n4 + 0) * BS_STRIDE + kk] = f2tf32(v.x);
            Bs[(n4 + 1) * BS_STRIDE + kk] = f2tf32(v.y);
            Bs[(n4 + 2) * BS_STRIDE + kk] = f2tf32(v.z);
            Bs[(n4 + 3) * BS_STRIDE + kk] = f2tf32(v.w);
        } else {
            const int n   = t >> 2;              // [0,64)
            const int kk4 = (t & 3) << 2;        // {0,4,8,12}
            const float4 v = *(const float4*)(B + (size_t)(n0 + n) * ldb + k0 + kk4);
            uint4 u;
            u.x = f2tf32(v.x); u.y = f2tf32(v.y);
            u.z = f2tf32(v.z); u.w = f2tf32(v.w);
            *(uint4*)&Bs[n * BS_STRIDE + kk4] = u;
        }
        __syncthreads();

        // ---- compute: 2 k-steps of 8 ----
#pragma unroll
        for (int ks = 0; ks < 16; ks += 8) {
            uint32_t a[2][4], b[4][2];
#pragma unroll
            for (int i = 0; i < 2; i++) {
                const int r = warp_m + i * 16;
                a[i][0] = As[(r + g)     * AS_STRIDE + ks + t4];
                a[i][1] = As[(r + g + 8) * AS_STRIDE + ks + t4];
                a[i][2] = As[(r + g)     * AS_STRIDE + ks + t4 + 4];
                a[i][3] = As[(r + g + 8) * AS_STRIDE + ks + t4 + 4];
            }
#pragma unroll
            for (int j = 0; j < 4; j++) {
                const int c = warp_n + j * 8 + g;
                b[j][0] = Bs[c * BS_STRIDE + ks + t4];
                b[j][1] = Bs[c * BS_STRIDE + ks + t4 + 4];
            }
#pragma unroll
            for (int i = 0; i < 2; i++)
#pragma unroll
                for (int j = 0; j < 4; j++)
                    mma_tf32(acc[i][j][0], acc[i][j][1], acc[i][j][2], acc[i][j][3],
                             a[i][0], a[i][1], a[i][2], a[i][3],
                             b[j][0], b[j][1]);
        }
        __syncthreads();
    }
}

// ---------------------------------------------------------------------------
// Fused QKV projection: grid (16, 32, 3); z selects (src, W, bias, dst).
// C[m][n] = A @ W + bias, all [4096 x 1024] x [1024 x 1024].
// ---------------------------------------------------------------------------
__global__ __launch_bounds__(256) void qkv_proj_kernel(
    const float* __restrict__ q,  const float* __restrict__ k,  const float* __restrict__ v,
    const float* __restrict__ Wq, const float* __restrict__ Wk, const float* __restrict__ Wv,
    const float* __restrict__ bq, const float* __restrict__ bk, const float* __restrict__ bv)
{
    __shared__ uint32_t As[128 * AS_STRIDE];
    __shared__ uint32_t Bs[64 * BS_STRIDE];

    const float* A; const float* W; const float* bias; float* C;
    if (blockIdx.z == 0)      { A = q; W = Wq; bias = bq; C = g_Qp; }
    else if (blockIdx.z == 1) { A = k; W = Wk; bias = bk; C = g_Kp; }
    else                      { A = v; W = Wv; bias = bv; C = g_Vp; }

    const int m0 = blockIdx.y * 128;
    const int n0 = blockIdx.x * 64;

    float acc[2][4][4];
#pragma unroll
    for (int i = 0; i < 2; i++)
#pragma unroll
        for (int j = 0; j < 4; j++)
#pragma unroll
            for (int r = 0; r < 4; r++) acc[i][j][r] = 0.f;

    gemm_tile_tf32<true>(A, DM_, W, DM_, DM_, m0, n0, As, Bs, acc);

    const int lane = threadIdx.x & 31, wid = threadIdx.x >> 5;
    const int warp_m = (wid & 3) * 32, warp_n = (wid >> 2) * 32;
    const int g = lane >> 2, t4 = lane & 3;
#pragma unroll
    for (int i = 0; i < 2; i++) {
        const int mrow = m0 + warp_m + i * 16 + g;
#pragma unroll
        for (int j = 0; j < 4; j++) {
            const int n = n0 + warp_n + j * 8 + 2 * t4;
            const float b0 = bias[n], b1 = bias[n + 1];
            *(float2*)(C + (size_t)mrow * DM_ + n) =
                make_float2(acc[i][j][0] + b0, acc[i][j][1] + b1);
            *(float2*)(C + (size_t)(mrow + 8) * DM_ + n) =
                make_float2(acc[i][j][2] + b0, acc[i][j][3] + b1);
        }
    }
}

// ---------------------------------------------------------------------------
// Output projection: out = g_ctx @ Wo + bo. grid (16, 32).
// ---------------------------------------------------------------------------
__global__ __launch_bounds__(256) void out_proj_kernel(
    const float* __restrict__ Wo, const float* __restrict__ bo, float* __restrict__ out)
{
    __shared__ uint32_t As[128 * AS_STRIDE];
    __shared__ uint32_t Bs[64 * BS_STRIDE];

    const int m0 = blockIdx.y * 128;
    const int n0 = blockIdx.x * 64;

    float acc[2][4][4];
#pragma unroll
    for (int i = 0; i < 2; i++)
#pragma unroll
        for (int j = 0; j < 4; j++)
#pragma unroll
            for (int r = 0; r < 4; r++) acc[i][j][r] = 0.f;

    gemm_tile_tf32<true>(g_ctx, DM_, Wo, DM_, DM_, m0, n0, As, Bs, acc);

    const int lane = threadIdx.x & 31, wid = threadIdx.x >> 5;
    const int warp_m = (wid & 3) * 32, warp_n = (wid >> 2) * 32;
    const int g = lane >> 2, t4 = lane & 3;
#pragma unroll
    for (int i = 0; i < 2; i++) {
        const int mrow = m0 + warp_m + i * 16 + g;
#pragma unroll
        for (int j = 0; j < 4; j++) {
            const int n = n0 + warp_n + j * 8 + 2 * t4;
            const float b0 = bo[n], b1 = bo[n + 1];
            *(float2*)(out + (size_t)mrow * DM_ + n) =
                make_float2(acc[i][j][0] + b0, acc[i][j][1] + b1);
            *(float2*)(out + (size_t)(mrow + 8) * DM_ + n) =
                make_float2(acc[i][j][2] + b0, acc[i][j][3] + b1);
        }
    }
}

// ---------------------------------------------------------------------------
// Scores (NT): per z: attn_z[q][kk] = (1/8) sum_d Qh[q][d] Kh[kk][d]
// grid (32, 16, 32). A = Qp slice (lda=1024), B = Kp slice ([N][K], ldb=1024).
// ---------------------------------------------------------------------------
__global__ __launch_bounds__(256) void scores_kernel_mma(float* __restrict__ attn) {
    __shared__ uint32_t As[128 * AS_STRIDE];
    __shared__ uint32_t Bs[64 * BS_STRIDE];

    const int z = blockIdx.z;
    const int b = z >> 4, h = z & 15;
    const float* Aq = g_Qp + (size_t)b * S_ * DM_ + h * DK_;
    const float* Bk = g_Kp + (size_t)b * S_ * DM_ + h * DK_;
    float* Cc = attn + (size_t)z * S_ * S_;

    const int m0 = blockIdx.y * 128;
    const int n0 = blockIdx.x * 64;

    float acc[2][4][4];
#pragma unroll
    for (int i = 0; i < 2; i++)
#pragma unroll
        for (int j = 0; j < 4; j++)
#pragma unroll
            for (int r = 0; r < 4; r++) acc[i][j][r] = 0.f;

    gemm_tile_tf32<false>(Aq, DM_, Bk, DM_, DK_, m0, n0, As, Bs, acc);

    const int lane = threadIdx.x & 31, wid = threadIdx.x >> 5;
    const int warp_m = (wid & 3) * 32, warp_n = (wid >> 2) * 32;
    const int g = lane >> 2, t4 = lane & 3;
#pragma unroll
    for (int i = 0; i < 2; i++) {
        const int mrow = m0 + warp_m + i * 16 + g;
#pragma unroll
        for (int j = 0; j < 4; j++) {
            const int n = n0 + warp_n + j * 8 + 2 * t4;
            *(float2*)(Cc + (size_t)mrow * S_ + n) =
                make_float2(acc[i][j][0] * 0.125f, acc[i][j][1] * 0.125f);
            *(float2*)(Cc + (size_t)(mrow + 8) * S_ + n) =
                make_float2(acc[i][j][2] * 0.125f, acc[i][j][3] * 0.125f);
        }
    }
}

// ---------------------------------------------------------------------------
// Context (NN): per z: ctx[s][c] = sum_k attn_z[s][k] * Vh[k][c]
// grid (1, 16, 32). A = attn (lda=2048), B = Vp slice ([K][N], ldb=1024, TRANSB).
// ---------------------------------------------------------------------------
__global__ __launch_bounds__(256) void ctx_kernel_mma(const float* __restrict__ attn) {
    __shared__ uint32_t As[128 * AS_STRIDE];
    __shared__ uint32_t Bs[64 * BS_STRIDE];

    const int z = blockIdx.z;
    const int b = z >> 4, h = z & 15;
    const float* Aa = attn + (size_t)z * S_ * S_;
    const float* Bv = g_Vp + (size_t)b * S_ * DM_ + h * DK_;
    float*       Cc = g_ctx + (size_t)b * S_ * DM_ + h * DK_;

    const int m0 = blockIdx.y * 128;

    float acc[2][4][4];
#pragma unroll
    for (int i = 0; i < 2; i++)
#pragma unroll
        for (int j = 0; j < 4; j++)
#pragma unroll
            for (int r = 0; r < 4; r++) acc[i][j][r] = 0.f;

    gemm_tile_tf32<true>(Aa, S_, Bv, DM_, S_, m0, 0, As, Bs, acc);

    const int lane = threadIdx.x & 31, wid = threadIdx.x >> 5;
    const int warp_m = (wid & 3) * 32, warp_n = (wid >> 2) * 32;
    const int g = lane >> 2, t4 = lane & 3;
#pragma unroll
    for (int i = 0; i < 2; i++) {
        const int mrow = m0 + warp_m + i * 16 + g;
#pragma unroll
        for (int j = 0; j < 4; j++) {
            const int n = warp_n + j * 8 + 2 * t4;
            *(float2*)(Cc + (size_t)mrow * DM_ + n) =
                make_float2(acc[i][j][0], acc[i][j][1]);
            *(float2*)(Cc + (size_t)(mrow + 8) * DM_ + n) =
                make_float2(acc[i][j][2], acc[i][j][3]);
        }
    }
}

// ---------------------------------------------------------------------------
// Row softmax over 2048, in place, float4-vectorized. One block per row.
// ---------------------------------------------------------------------------
__global__ __launch_bounds__(256) void softmax_kernel(float* __restrict__ attn) {
    float4* p4 = (float4*)(attn + (size_t)blockIdx.x * S_);
    const int t = threadIdx.x;
    __shared__ float red[256];

    float4 u = p4[t * 2], w = p4[t * 2 + 1];
    float mx = fmaxf(fmaxf(fmaxf(u.x, u.y), fmaxf(u.z, u.w)),
                     fmaxf(fmaxf(w.x, w.y), fmaxf(w.z, w.w)));
    red[t] = mx;
    __syncthreads();
    for (int o = 128; o > 0; o >>= 1) {
        if (t < o) red[t] = fmaxf(red[t], red[t + o]);
        __syncthreads();
    }
    mx = red[0];
    __syncthreads();

    u.x = expf(u.x - mx); u.y = expf(u.y - mx); u.z = expf(u.z - mx); u.w = expf(u.w - mx);
    w.x = expf(w.x - mx); w.y = expf(w.y - mx); w.z = expf(w.z - mx); w.w = expf(w.w - mx);
    float sm = u.x + u.y + u.z + u.w + w.x + w.y + w.z + w.w;
    red[t] = sm;
    __syncthreads();
    for (int o = 128; o > 0; o >>= 1) {
        if (t < o) red[t] += red[t + o];
        __syncthreads();
    }
    const float inv = 1.0f / red[0];
    u.x *= inv; u.y *= inv; u.z *= inv; u.w *= inv;
    w.x *= inv; w.y *= inv; w.z *= inv; w.w *= inv;
    p4[t * 2] = u; p4[t * 2 + 1] = w;
}

// ---------------------------------------------------------------------------
// Launch. Inputs: signature order. Outputs: output first, then attn (proven R8).
// ---------------------------------------------------------------------------
extern "C" void kernel_launch(void* const* d_in, const int* in_sizes, int n_in,
                              void* d_out, int out_size) {
    const float* q  = (const float*)d_in[0];
    const float* k  = (const float*)d_in[1];
    const float* v  = (const float*)d_in[2];
    const float* Wq = (const float*)d_in[3];
    const float* bq = (const float*)d_in[4];
    const float* Wk = (const float*)d_in[5];
    const float* bk = (const float*)d_in[6];
    const float* Wv = (const float*)d_in[7];
    const float* bv = (const float*)d_in[8];
    const float* Wo = (const float*)d_in[9];
    const float* bo = (const float*)d_in[10];

    float* out;
    float* attn;
    if (out_size == N_ACT) {
        float* sa; cudaGetSymbolAddress((void**)&sa, g_attn_scratch);
        out = (float*)d_out; attn = sa;
    } else if (out_size == N_ATTN) {
        float* so; cudaGetSymbolAddress((void**)&so, g_out_scratch);
        attn = (float*)d_out; out = so;
    } else {
        out  = (float*)d_out;
        attn = (float*)d_out + N_ACT;
    }

    dim3 blk(256);

    dim3 gqkv(DM_ / 64, BS_TOK / 128, 3);            // (16, 32, 3)
    qkv_proj_kernel<<<gqkv, blk>>>(q, k, v, Wq, Wk, Wv, bq, bk, bv);

    dim3 gsc(S_ / 64, S_ / 128, NBH);                // (32, 16, 32)
    scores_kernel_mma<<<gsc, blk>>>(attn);

    softmax_kernel<<<(unsigned)(NBH * S_), blk>>>(attn);   // 65536 rows

    dim3 gctx(1, S_ / 128, NBH);                     // (1, 16, 32)
    ctx_kernel_mma<<<gctx, blk>>>(attn);

    dim3 gout(DM_ / 64, BS_TOK / 128);               // (16, 32)
    out_proj_kernel<<<gout, blk>>>(Wo, bo, out);
}

// round 16
// speedup vs baseline: 2.5594x; 1.1598x over previous
#include <cuda_runtime.h>
#include <math.h>
#include <stdint.h>

// Problem constants
#define B_   2
#define S_   2048
#define DM_  1024
#define H_   16
#define DK_  64
#define BS_TOK 4096                // B*S
#define NBH  32                    // B*H

#define N_ACT  4194304             // BS_TOK * DM_
#define N_ATTN 134217728           // NBH * S * S

// Scratch (module-load allocated; legal)
__device__ float g_Qp[N_ACT];          // [BS, D]
__device__ float g_Kp[N_ACT];          // [BS, D]
__device__ float g_Vp[N_ACT];          // [BS, D]
__device__ float g_ctx[N_ACT];         // [BS, D]
__device__ float g_attn_scratch[N_ATTN];
__device__ float g_out_scratch [N_ACT];

// ---------------------------------------------------------------------------
// tf32 helpers
// ---------------------------------------------------------------------------
__device__ __forceinline__ uint32_t f2tf32(float x) {
    uint32_t r;
    asm("cvt.rna.tf32.f32 %0, %1;" : "=r"(r) : "f"(x));
    return r;
}

__device__ __forceinline__ void mma_tf32(float& c0, float& c1, float& c2, float& c3,
                                         uint32_t a0, uint32_t a1, uint32_t a2, uint32_t a3,
                                         uint32_t b0, uint32_t b1) {
    asm("mma.sync.aligned.m16n8k8.row.col.f32.tf32.tf32.f32 "
        "{%0,%1,%2,%3}, {%4,%5,%6,%7}, {%8,%9}, {%0,%1,%2,%3};"
        : "+f"(c0), "+f"(c1), "+f"(c2), "+f"(c3)
        : "r"(a0), "r"(a1), "r"(a2), "r"(a3), "r"(b0), "r"(b1));
}

// ===========================================================================
// Projection GEMM machinery (unchanged from R12, proven)
// Block tile 128x64x16, 8 warps 4(M)x2(N), warp 32x32 (2x4 m16n8k8 atoms).
// ===========================================================================
#define AS_STRIDE 20
#define BS_STRIDE 20

template <bool TRANSB>
__device__ __forceinline__ void gemm_tile_tf32(
    const float* __restrict__ A, int lda,
    const float* __restrict__ B, int ldb,
    int K, int m0, int n0,
    uint32_t* As, uint32_t* Bs,
    float acc[2][4][4])
{
    const int t    = threadIdx.x;
    const int lane = t & 31;
    const int wid  = t >> 5;
    const int warp_m = (wid & 3) * 32;
    const int warp_n = (wid >> 2) * 32;
    const int g  = lane >> 2;
    const int t4 = lane & 3;

    for (int k0 = 0; k0 < K; k0 += 16) {
#pragma unroll
        for (int rep = 0; rep < 2; rep++) {
            const int lin = t + rep * 256;
            const int m   = lin >> 2;
            const int k4  = (lin & 3) << 2;
            const float4 v = *(const float4*)(A + (size_t)(m0 + m) * lda + k0 + k4);
            uint4 u;
            u.x = f2tf32(v.x); u.y = f2tf32(v.y);
            u.z = f2tf32(v.z); u.w = f2tf32(v.w);
            *(uint4*)&As[m * AS_STRIDE + k4] = u;
        }
        if (TRANSB) {
            const int kk = t >> 4;
            const int n4 = (t & 15) << 2;
            const float4 v = *(const float4*)(B + (size_t)(k0 + kk) * ldb + n0 + n4);
            Bs[(n4 + 0) * BS_STRIDE + kk] = f2tf32(v.x);
            Bs[(n4 + 1) * BS_STRIDE + kk] = f2tf32(v.y);
            Bs[(n4 + 2) * BS_STRIDE + kk] = f2tf32(v.z);
            Bs[(n4 + 3) * BS_STRIDE + kk] = f2tf32(v.w);
        } else {
            const int n   = t >> 2;
            const int kk4 = (t & 3) << 2;
            const float4 v = *(const float4*)(B + (size_t)(n0 + n) * ldb + k0 + kk4);
            uint4 u;
            u.x = f2tf32(v.x); u.y = f2tf32(v.y);
            u.z = f2tf32(v.z); u.w = f2tf32(v.w);
            *(uint4*)&Bs[n * BS_STRIDE + kk4] = u;
        }
        __syncthreads();
#pragma unroll
        for (int ks = 0; ks < 16; ks += 8) {
            uint32_t a[2][4], b[4][2];
#pragma unroll
            for (int i = 0; i < 2; i++) {
                const int r = warp_m + i * 16;
                a[i][0] = As[(r + g)     * AS_STRIDE + ks + t4];
                a[i][1] = As[(r + g + 8) * AS_STRIDE + ks + t4];
                a[i][2] = As[(r + g)     * AS_STRIDE + ks + t4 + 4];
                a[i][3] = As[(r + g + 8) * AS_STRIDE + ks + t4 + 4];
            }
#pragma unroll
            for (int j = 0; j < 4; j++) {
                const int c = warp_n + j * 8 + g;
                b[j][0] = Bs[c * BS_STRIDE + ks + t4];
                b[j][1] = Bs[c * BS_STRIDE + ks + t4 + 4];
            }
#pragma unroll
            for (int i = 0; i < 2; i++)
#pragma unroll
                for (int j = 0; j < 4; j++)
                    mma_tf32(acc[i][j][0], acc[i][j][1], acc[i][j][2], acc[i][j][3],
                             a[i][0], a[i][1], a[i][2], a[i][3],
                             b[j][0], b[j][1]);
        }
        __syncthreads();
    }
}

__global__ __launch_bounds__(256) void qkv_proj_kernel(
    const float* __restrict__ q,  const float* __restrict__ k,  const float* __restrict__ v,
    const float* __restrict__ Wq, const float* __restrict__ Wk, const float* __restrict__ Wv,
    const float* __restrict__ bq, const float* __restrict__ bk, const float* __restrict__ bv)
{
    __shared__ uint32_t As[128 * AS_STRIDE];
    __shared__ uint32_t Bs[64 * BS_STRIDE];

    const float* A; const float* W; const float* bias; float* C;
    if (blockIdx.z == 0)      { A = q; W = Wq; bias = bq; C = g_Qp; }
    else if (blockIdx.z == 1) { A = k; W = Wk; bias = bk; C = g_Kp; }
    else                      { A = v; W = Wv; bias = bv; C = g_Vp; }

    const int m0 = blockIdx.y * 128;
    const int n0 = blockIdx.x * 64;

    float acc[2][4][4];
#pragma unroll
    for (int i = 0; i < 2; i++)
#pragma unroll
        for (int j = 0; j < 4; j++)
#pragma unroll
            for (int r = 0; r < 4; r++) acc[i][j][r] = 0.f;

    gemm_tile_tf32<true>(A, DM_, W, DM_, DM_, m0, n0, As, Bs, acc);

    const int lane = threadIdx.x & 31, wid = threadIdx.x >> 5;
    const int warp_m = (wid & 3) * 32, warp_n = (wid >> 2) * 32;
    const int g = lane >> 2, t4 = lane & 3;
#pragma unroll
    for (int i = 0; i < 2; i++) {
        const int mrow = m0 + warp_m + i * 16 + g;
#pragma unroll
        for (int j = 0; j < 4; j++) {
            const int n = n0 + warp_n + j * 8 + 2 * t4;
            const float b0 = bias[n], b1 = bias[n + 1];
            *(float2*)(C + (size_t)mrow * DM_ + n) =
                make_float2(acc[i][j][0] + b0, acc[i][j][1] + b1);
            *(float2*)(C + (size_t)(mrow + 8) * DM_ + n) =
                make_float2(acc[i][j][2] + b0, acc[i][j][3] + b1);
        }
    }
}

__global__ __launch_bounds__(256) void out_proj_kernel(
    const float* __restrict__ Wo, const float* __restrict__ bo, float* __restrict__ out)
{
    __shared__ uint32_t As[128 * AS_STRIDE];
    __shared__ uint32_t Bs[64 * BS_STRIDE];

    const int m0 = blockIdx.y * 128;
    const int n0 = blockIdx.x * 64;

    float acc[2][4][4];
#pragma unroll
    for (int i = 0; i < 2; i++)
#pragma unroll
        for (int j = 0; j < 4; j++)
#pragma unroll
            for (int r = 0; r < 4; r++) acc[i][j][r] = 0.f;

    gemm_tile_tf32<true>(g_ctx, DM_, Wo, DM_, DM_, m0, n0, As, Bs, acc);

    const int lane = threadIdx.x & 31, wid = threadIdx.x >> 5;
    const int warp_m = (wid & 3) * 32, warp_n = (wid >> 2) * 32;
    const int g = lane >> 2, t4 = lane & 3;
#pragma unroll
    for (int i = 0; i < 2; i++) {
        const int mrow = m0 + warp_m + i * 16 + g;
#pragma unroll
        for (int j = 0; j < 4; j++) {
            const int n = n0 + warp_n + j * 8 + 2 * t4;
            const float b0 = bo[n], b1 = bo[n + 1];
            *(float2*)(out + (size_t)mrow * DM_ + n) =
                make_float2(acc[i][j][0] + b0, acc[i][j][1] + b1);
            *(float2*)(out + (size_t)(mrow + 8) * DM_ + n) =
                make_float2(acc[i][j][2] + b0, acc[i][j][3] + b1);
        }
    }
}

// ===========================================================================
// Fused attention: per CTA = one (b,h) x 128 q-rows.
//   Pass A: stream K tiles, S = (Q K^T)/8 via mma, online row (max, sumexp).
//   Reduce stats (shfl over t4, smem over the 2 n-warps).
//   Pass B: recompute S, P = exp(s-M)/Z, stage P in smem, write attn (float4
//   coalesced), and accumulate ctx = P V with P fed back as mma A-operand.
// Smem strides: 68 words (bank-conflict-free for the fragment patterns).
// ===========================================================================
#define QS_STRIDE 68
#define KS_STRIDE 68
#define VS_STRIDE 68
#define PS_STRIDE 68

__global__ __launch_bounds__(256) void fused_attn_kernel(float* __restrict__ attn) {
    extern __shared__ uint32_t sm[];
    uint32_t* Qs   = sm;                          // 128*68 tf32
    uint32_t* Ks   = Qs + 128 * QS_STRIDE;        // 64*68 tf32 (Ks[key][dim])
    uint32_t* Vs   = Ks + 64 * KS_STRIDE;         // 64*68 tf32 (Vs[dim][key])
    float*    Ps   = (float*)(Vs + 64 * VS_STRIDE); // 128*68 fp32 (P[q][key])
    float*    partM = Ps + 128 * PS_STRIDE;       // 2*128
    float*    partS = partM + 256;                // 2*128
    float*    rowM  = partS + 256;                // 128
    float*    rowI  = rowM + 128;                 // 128

    const int t    = threadIdx.x;
    const int lane = t & 31;
    const int wid  = t >> 5;
    const int warp_m = (wid & 3) * 32;
    const int warp_n = (wid >> 2) * 32;
    const int wn   = wid >> 2;
    const int g  = lane >> 2;
    const int t4 = lane & 3;

    const int m0 = blockIdx.x * 128;              // q-block
    const int z  = blockIdx.y;                    // b*16 + h
    const int b  = z >> 4, h = z & 15;

    const float* Qp = g_Qp + (size_t)b * S_ * DM_ + h * DK_;
    const float* Kp = g_Kp + (size_t)b * S_ * DM_ + h * DK_;
    const float* Vp = g_Vp + (size_t)b * S_ * DM_ + h * DK_;
    float* attnz    = attn  + (size_t)z * S_ * S_;
    float* Cc       = g_ctx + (size_t)b * S_ * DM_ + h * DK_;

    // ---- load Q tile [128 x 64] (tf32) ----
#pragma unroll
    for (int it = 0; it < 8; it++) {
        const int idx = t + it * 256;             // [0,2048)
        const int r  = idx >> 4;
        const int c4 = (idx & 15) << 2;
        const float4 v = *(const float4*)(Qp + (size_t)(m0 + r) * DM_ + c4);
        uint4 u;
        u.x = f2tf32(v.x); u.y = f2tf32(v.y);
        u.z = f2tf32(v.z); u.w = f2tf32(v.w);
        *(uint4*)&Qs[r * QS_STRIDE + c4] = u;
    }
    __syncthreads();

    float mloc[4], sloc[4];
#pragma unroll
    for (int s = 0; s < 4; s++) { mloc[s] = -INFINITY; sloc[s] = 0.f; }

    // ======================= PASS A: stats =======================
    for (int n0 = 0; n0 < S_; n0 += 64) {
        // fill Ks[key][dim]
#pragma unroll
        for (int it = 0; it < 4; it++) {
            const int idx = t + it * 256;         // [0,1024)
            const int n  = idx >> 4;
            const int c4 = (idx & 15) << 2;
            const float4 v = *(const float4*)(Kp + (size_t)(n0 + n) * DM_ + c4);
            uint4 u;
            u.x = f2tf32(v.x); u.y = f2tf32(v.y);
            u.z = f2tf32(v.z); u.w = f2tf32(v.w);
            *(uint4*)&Ks[n * KS_STRIDE + c4] = u;
        }
        __syncthreads();

        float acc[2][4][4];
#pragma unroll
        for (int i = 0; i < 2; i++)
#pragma unroll
            for (int j = 0; j < 4; j++)
#pragma unroll
                for (int r = 0; r < 4; r++) acc[i][j][r] = 0.f;

#pragma unroll
        for (int ks = 0; ks < 64; ks += 8) {
            uint32_t a[2][4], bb[4][2];
#pragma unroll
            for (int i = 0; i < 2; i++) {
                const int r = warp_m + i * 16;
                a[i][0] = Qs[(r + g)     * QS_STRIDE + ks + t4];
                a[i][1] = Qs[(r + g + 8) * QS_STRIDE + ks + t4];
                a[i][2] = Qs[(r + g)     * QS_STRIDE + ks + t4 + 4];
                a[i][3] = Qs[(r + g + 8) * QS_STRIDE + ks + t4 + 4];
            }
#pragma unroll
            for (int j = 0; j < 4; j++) {
                const int c = warp_n + j * 8 + g;
                bb[j][0] = Ks[c * KS_STRIDE + ks + t4];
                bb[j][1] = Ks[c * KS_STRIDE + ks + t4 + 4];
            }
#pragma unroll
            for (int i = 0; i < 2; i++)
#pragma unroll
                for (int j = 0; j < 4; j++)
                    mma_tf32(acc[i][j][0], acc[i][j][1], acc[i][j][2], acc[i][j][3],
                             a[i][0], a[i][1], a[i][2], a[i][3],
                             bb[j][0], bb[j][1]);
        }
        __syncthreads();

        // online stats (registers only); slot = i*2 + half (half: 0->row g, 1->row g+8)
#pragma unroll
        for (int i = 0; i < 2; i++) {
#pragma unroll
            for (int half = 0; half < 2; half++) {
                const int slot = i * 2 + half;
                float vals[8];
                float tm = -INFINITY;
#pragma unroll
                for (int j = 0; j < 4; j++) {
                    vals[2 * j]     = acc[i][j][half * 2]     * 0.125f;
                    vals[2 * j + 1] = acc[i][j][half * 2 + 1] * 0.125f;
                    tm = fmaxf(tm, fmaxf(vals[2 * j], vals[2 * j + 1]));
                }
                const float mnew = fmaxf(mloc[slot], tm);
                float ssum = 0.f;
#pragma unroll
                for (int e = 0; e < 8; e++) ssum += __expf(vals[e] - mnew);
                sloc[slot] = sloc[slot] * __expf(mloc[slot] - mnew) + ssum;
                mloc[slot] = mnew;
            }
        }
    }

    // ---- reduce stats across t4 lanes ----
#pragma unroll
    for (int s = 0; s < 4; s++) {
#pragma unroll
        for (int off = 1; off <= 2; off <<= 1) {
            const float mo = __shfl_xor_sync(0xFFFFFFFFu, mloc[s], off);
            const float so = __shfl_xor_sync(0xFFFFFFFFu, sloc[s], off);
            const float M = fmaxf(mloc[s], mo);
            sloc[s] = sloc[s] * __expf(mloc[s] - M) + so * __expf(mo - M);
            mloc[s] = M;
        }
    }
    if (t4 == 0) {
        const int rows[4] = { warp_m + g, warp_m + 8 + g, warp_m + 16 + g, warp_m + 24 + g };
#pragma unroll
        for (int s = 0; s < 4; s++) {
            partM[wn * 128 + rows[s]] = mloc[s];
            partS[wn * 128 + rows[s]] = sloc[s];
        }
    }
    __syncthreads();
    if (t < 128) {
        const float m0_ = partM[t], m1_ = partM[128 + t];
        const float s0_ = partS[t], s1_ = partS[128 + t];
        const float M = fmaxf(m0_, m1_);
        const float Z = s0_ * __expf(m0_ - M) + s1_ * __expf(m1_ - M);
        rowM[t] = M;
        rowI[t] = 1.0f / Z;
    }
    __syncthreads();

    float fM[4], fI[4];
    {
        const int rows[4] = { warp_m + g, warp_m + 8 + g, warp_m + 16 + g, warp_m + 24 + g };
#pragma unroll
        for (int s = 0; s < 4; s++) { fM[s] = rowM[rows[s]]; fI[s] = rowI[rows[s]]; }
    }

    // ctx accumulators persist across pass B
    float cacc[2][4][4];
#pragma unroll
    for (int i = 0; i < 2; i++)
#pragma unroll
        for (int j = 0; j < 4; j++)
#pragma unroll
            for (int r = 0; r < 4; r++) cacc[i][j][r] = 0.f;

    // ======================= PASS B: P write + ctx =======================
    for (int n0 = 0; n0 < S_; n0 += 64) {
        // fill Ks[key][dim]
#pragma unroll
        for (int it = 0; it < 4; it++) {
            const int idx = t + it * 256;
            const int n  = idx >> 4;
            const int c4 = (idx & 15) << 2;
            const float4 v = *(const float4*)(Kp + (size_t)(n0 + n) * DM_ + c4);
            uint4 u;
            u.x = f2tf32(v.x); u.y = f2tf32(v.y);
            u.z = f2tf32(v.z); u.w = f2tf32(v.w);
            *(uint4*)&Ks[n * KS_STRIDE + c4] = u;
        }
        // fill Vs[dim][key] (transposed; lanes carry distinct keys -> conflict-free)
#pragma unroll
        for (int it = 0; it < 4; it++) {
            const int idx = t + it * 256;         // [0,1024)
            const int kk = idx & 63;              // key
            const int d4 = (idx >> 6) << 2;       // dim group {0,4,..,60}
            const float4 v = *(const float4*)(Vp + (size_t)(n0 + kk) * DM_ + d4);
            Vs[(d4 + 0) * VS_STRIDE + kk] = f2tf32(v.x);
            Vs[(d4 + 1) * VS_STRIDE + kk] = f2tf32(v.y);
            Vs[(d4 + 2) * VS_STRIDE + kk] = f2tf32(v.z);
            Vs[(d4 + 3) * VS_STRIDE + kk] = f2tf32(v.w);
        }
        __syncthreads();

        // recompute S tile
        float acc[2][4][4];
#pragma unroll
        for (int i = 0; i < 2; i++)
#pragma unroll
            for (int j = 0; j < 4; j++)
#pragma unroll
                for (int r = 0; r < 4; r++) acc[i][j][r] = 0.f;

#pragma unroll
        for (int ks = 0; ks < 64; ks += 8) {
            uint32_t a[2][4], bb[4][2];
#pragma unroll
            for (int i = 0; i < 2; i++) {
                const int r = warp_m + i * 16;
                a[i][0] = Qs[(r + g)     * QS_STRIDE + ks + t4];
                a[i][1] = Qs[(r + g + 8) * QS_STRIDE + ks + t4];
                a[i][2] = Qs[(r + g)     * QS_STRIDE + ks + t4 + 4];
                a[i][3] = Qs[(r + g + 8) * QS_STRIDE + ks + t4 + 4];
            }
#pragma unroll
            for (int j = 0; j < 4; j++) {
                const int c = warp_n + j * 8 + g;
                bb[j][0] = Ks[c * KS_STRIDE + ks + t4];
                bb[j][1] = Ks[c * KS_STRIDE + ks + t4 + 4];
            }
#pragma unroll
            for (int i = 0; i < 2; i++)
#pragma unroll
                for (int j = 0; j < 4; j++)
                    mma_tf32(acc[i][j][0], acc[i][j][1], acc[i][j][2], acc[i][j][3],
                             a[i][0], a[i][1], a[i][2], a[i][3],
                             bb[j][0], bb[j][1]);
        }

        // P = exp(s - M) * invZ  -> stage in Ps
#pragma unroll
        for (int i = 0; i < 2; i++) {
            const int r0 = warp_m + i * 16 + g;
            const int r1 = r0 + 8;
            const int s0_ = i * 2, s1_ = i * 2 + 1;
#pragma unroll
            for (int j = 0; j < 4; j++) {
                const int col = warp_n + j * 8 + 2 * t4;
                const float p00 = __expf(acc[i][j][0] * 0.125f - fM[s0_]) * fI[s0_];
                const float p01 = __expf(acc[i][j][1] * 0.125f - fM[s0_]) * fI[s0_];
                const float p10 = __expf(acc[i][j][2] * 0.125f - fM[s1_]) * fI[s1_];
                const float p11 = __expf(acc[i][j][3] * 0.125f - fM[s1_]) * fI[s1_];
                *(float2*)&Ps[r0 * PS_STRIDE + col] = make_float2(p00, p01);
                *(float2*)&Ps[r1 * PS_STRIDE + col] = make_float2(p10, p11);
            }
        }
        __syncthreads();

        // write attn tile (coalesced float4 from Ps)
#pragma unroll
        for (int it = 0; it < 8; it++) {
            const int idx = t + it * 256;         // [0,2048)
            const int r  = idx >> 4;
            const int c4 = (idx & 15) << 2;
            *(float4*)(attnz + (size_t)(m0 + r) * S_ + n0 + c4) =
                *(float4*)&Ps[r * PS_STRIDE + c4];
        }

        // ctx += P @ V  (A from Ps with tf32 convert, B from Vs)
#pragma unroll
        for (int ks = 0; ks < 64; ks += 8) {
            uint32_t a[2][4], bb[4][2];
#pragma unroll
            for (int i = 0; i < 2; i++) {
                const int r = warp_m + i * 16;
                a[i][0] = f2tf32(Ps[(r + g)     * PS_STRIDE + ks + t4]);
                a[i][1] = f2tf32(Ps[(r + g + 8) * PS_STRIDE + ks + t4]);
                a[i][2] = f2tf32(Ps[(r + g)     * PS_STRIDE + ks + t4 + 4]);
                a[i][3] = f2tf32(Ps[(r + g + 8) * PS_STRIDE + ks + t4 + 4]);
            }
#pragma unroll
            for (int j = 0; j < 4; j++) {
                const int c = warp_n + j * 8 + g;
                bb[j][0] = Vs[c * VS_STRIDE + ks + t4];
                bb[j][1] = Vs[c * VS_STRIDE + ks + t4 + 4];
            }
#pragma unroll
            for (int i = 0; i < 2; i++)
#pragma unroll
                for (int j = 0; j < 4; j++)
                    mma_tf32(cacc[i][j][0], cacc[i][j][1], cacc[i][j][2], cacc[i][j][3],
                             a[i][0], a[i][1], a[i][2], a[i][3],
                             bb[j][0], bb[j][1]);
        }
        __syncthreads();
    }

    // ---- write ctx [128 x 64] ----
#pragma unroll
    for (int i = 0; i < 2; i++) {
        const int mrow = m0 + warp_m + i * 16 + g;
#pragma unroll
        for (int j = 0; j < 4; j++) {
            const int n = warp_n + j * 8 + 2 * t4;
            *(float2*)(Cc + (size_t)mrow * DM_ + n) =
                make_float2(cacc[i][j][0], cacc[i][j][1]);
            *(float2*)(Cc + (size_t)(mrow + 8) * DM_ + n) =
                make_float2(cacc[i][j][2], cacc[i][j][3]);
        }
    }
}

#define FUSED_SMEM ((128*QS_STRIDE + 64*KS_STRIDE + 64*VS_STRIDE + 128*PS_STRIDE + 256 + 256 + 128 + 128) * 4)

// ---------------------------------------------------------------------------
// Launch. Inputs: signature order. Outputs: output first, then attn.
// ---------------------------------------------------------------------------
extern "C" void kernel_launch(void* const* d_in, const int* in_sizes, int n_in,
                              void* d_out, int out_size) {
    const float* q  = (const float*)d_in[0];
    const float* k  = (const float*)d_in[1];
    const float* v  = (const float*)d_in[2];
    const float* Wq = (const float*)d_in[3];
    const float* bq = (const float*)d_in[4];
    const float* Wk = (const float*)d_in[5];
    const float* bk = (const float*)d_in[6];
    const float* Wv = (const float*)d_in[7];
    const float* bv = (const float*)d_in[8];
    const float* Wo = (const float*)d_in[9];
    const float* bo = (const float*)d_in[10];

    float* out;
    float* attn;
    if (out_size == N_ACT) {
        float* sa; cudaGetSymbolAddress((void**)&sa, g_attn_scratch);
        out = (float*)d_out; attn = sa;
    } else if (out_size == N_ATTN) {
        float* so; cudaGetSymbolAddress((void**)&so, g_out_scratch);
        attn = (float*)d_out; out = so;
    } else {
        out  = (float*)d_out;
        attn = (float*)d_out + N_ACT;
    }

    static bool attr_set = false;
    if (!attr_set) {
        cudaFuncSetAttribute(fused_attn_kernel,
                             cudaFuncAttributeMaxDynamicSharedMemorySize, FUSED_SMEM);
        attr_set = true;
    }

    dim3 blk(256);

    dim3 gqkv(DM_ / 64, BS_TOK / 128, 3);            // (16, 32, 3)
    qkv_proj_kernel<<<gqkv, blk>>>(q, k, v, Wq, Wk, Wv, bq, bk, bv);

    dim3 gf(S_ / 128, NBH);                          // (16, 32)
    fused_attn_kernel<<<gf, blk, FUSED_SMEM>>>(attn);

    dim3 gout(DM_ / 64, BS_TOK / 128);               // (16, 32)
    out_proj_kernel<<<gout, blk>>>(Wo, bo, out);
}

// round 17
// speedup vs baseline: 2.9942x; 1.1699x over previous
#include <cuda_runtime.h>
#include <math.h>
#include <stdint.h>

// Problem constants
#define B_   2
#define S_   2048
#define DM_  1024
#define H_   16
#define DK_  64
#define BS_TOK 4096                // B*S
#define NBH  32                    // B*H

#define N_ACT  4194304             // BS_TOK * DM_
#define N_ATTN 134217728           // NBH * S * S

// Scratch (module-load allocated; legal)
__device__ float g_Qp[N_ACT];          // [BS, D]
__device__ float g_Kp[N_ACT];          // [BS, D]
__device__ float g_Vp[N_ACT];          // [BS, D]
__device__ float g_ctx[N_ACT];         // [BS, D]
__device__ float g_attn_scratch[N_ATTN];
__device__ float g_out_scratch [N_ACT];

// ---------------------------------------------------------------------------
// tf32 helpers
// ---------------------------------------------------------------------------
__device__ __forceinline__ uint32_t f2tf32(float x) {
    uint32_t r;
    asm("cvt.rna.tf32.f32 %0, %1;" : "=r"(r) : "f"(x));
    return r;
}

__device__ __forceinline__ void mma_tf32(float& c0, float& c1, float& c2, float& c3,
                                         uint32_t a0, uint32_t a1, uint32_t a2, uint32_t a3,
                                         uint32_t b0, uint32_t b1) {
    asm("mma.sync.aligned.m16n8k8.row.col.f32.tf32.tf32.f32 "
        "{%0,%1,%2,%3}, {%4,%5,%6,%7}, {%8,%9}, {%0,%1,%2,%3};"
        : "+f"(c0), "+f"(c1), "+f"(c2), "+f"(c3)
        : "r"(a0), "r"(a1), "r"(a2), "r"(a3), "r"(b0), "r"(b1));
}

// ===========================================================================
// Projection GEMM v2: C[4096,1024] = A[4096,1024] @ W[1024,1024] (+bias)
// Block tile 128(M) x 128(N) x 32(K), double-buffered smem, 256 threads.
// 8 warps as 2(M) x 4(N); warp tile 64x32 = 4 m-atoms x 4 n-atoms m16n8k8.
// As[m][k] stride 36 (banks 4g+t4: conflict-free).
// Bs[k][n] stride 136 (banks 8t4+g: conflict-free; B stored NON-transposed).
// One __syncthreads per 32-K stage; gmem prefetch in registers.
// ===========================================================================
#define PA_STRIDE 36
#define PB_STRIDE 136
#define PROJ_STAGE_WORDS (128 * PA_STRIDE + 32 * PB_STRIDE)   // 4608 + 4352 = 8960
#define PROJ_SMEM (2 * PROJ_STAGE_WORDS * 4)                  // 71680 bytes

__device__ __forceinline__ void proj_gemm_v2(
    const float* __restrict__ A, const float* __restrict__ W,
    int m0, int n0, uint32_t* sm, float acc[4][4][4])
{
    const int t    = threadIdx.x;
    const int lane = t & 31;
    const int wid  = t >> 5;
    const int warp_m = (wid & 1) * 64;
    const int warp_n = (wid >> 1) * 32;
    const int g  = lane >> 2;
    const int t4 = lane & 3;

    uint32_t* AsBuf[2] = { sm,                     sm + PROJ_STAGE_WORDS };
    uint32_t* BsBuf[2] = { sm + 128 * PA_STRIDE,   sm + PROJ_STAGE_WORDS + 128 * PA_STRIDE };

    // ---- prologue: fill stage 0 (k0 = 0) ----
#pragma unroll
    for (int it = 0; it < 4; it++) {
        const int lin = t + it * 256;                 // [0,1024)
        const int m  = lin >> 3;                      // [0,128)
        const int k4 = (lin & 7) << 2;                // [0,32)
        const float4 v = *(const float4*)(A + (size_t)(m0 + m) * DM_ + k4);
        uint4 u;
        u.x = f2tf32(v.x); u.y = f2tf32(v.y); u.z = f2tf32(v.z); u.w = f2tf32(v.w);
        *(uint4*)&AsBuf[0][m * PA_STRIDE + k4] = u;

        const int kk = lin >> 5;                      // [0,32)
        const int n4 = (lin & 31) << 2;               // [0,128)
        const float4 w = *(const float4*)(W + (size_t)kk * DM_ + n0 + n4);
        uint4 uw;
        uw.x = f2tf32(w.x); uw.y = f2tf32(w.y); uw.z = f2tf32(w.z); uw.w = f2tf32(w.w);
        *(uint4*)&BsBuf[0][kk * PB_STRIDE + n4] = uw;
    }
    __syncthreads();

    int cur = 0;
    for (int k0 = 0; k0 < DM_; k0 += 32) {
        const bool more = (k0 + 32) < DM_;
        float4 av[4], bv[4];
        if (more) {
#pragma unroll
            for (int it = 0; it < 4; it++) {
                const int lin = t + it * 256;
                const int m  = lin >> 3;
                const int k4 = (lin & 7) << 2;
                av[it] = *(const float4*)(A + (size_t)(m0 + m) * DM_ + k0 + 32 + k4);
                const int kk = lin >> 5;
                const int n4 = (lin & 31) << 2;
                bv[it] = *(const float4*)(W + (size_t)(k0 + 32 + kk) * DM_ + n0 + n4);
            }
        }

        const uint32_t* as = AsBuf[cur];
        const uint32_t* bs = BsBuf[cur];
#pragma unroll
        for (int ks = 0; ks < 32; ks += 8) {
            uint32_t a[4][4], b[4][2];
#pragma unroll
            for (int i = 0; i < 4; i++) {
                const int r = warp_m + i * 16;
                a[i][0] = as[(r + g)     * PA_STRIDE + ks + t4];
                a[i][1] = as[(r + g + 8) * PA_STRIDE + ks + t4];
                a[i][2] = as[(r + g)     * PA_STRIDE + ks + t4 + 4];
                a[i][3] = as[(r + g + 8) * PA_STRIDE + ks + t4 + 4];
            }
#pragma unroll
            for (int j = 0; j < 4; j++) {
                const int c = warp_n + j * 8 + g;
                b[j][0] = bs[(ks + t4)     * PB_STRIDE + c];
                b[j][1] = bs[(ks + t4 + 4) * PB_STRIDE + c];
            }
#pragma unroll
            for (int i = 0; i < 4; i++)
#pragma unroll
                for (int j = 0; j < 4; j++)
                    mma_tf32(acc[i][j][0], acc[i][j][1], acc[i][j][2], acc[i][j][3],
                             a[i][0], a[i][1], a[i][2], a[i][3],
                             b[j][0], b[j][1]);
        }

        if (more) {
            uint32_t* asn = AsBuf[cur ^ 1];
            uint32_t* bsn = BsBuf[cur ^ 1];
#pragma unroll
            for (int it = 0; it < 4; it++) {
                const int lin = t + it * 256;
                const int m  = lin >> 3;
                const int k4 = (lin & 7) << 2;
                uint4 u;
                u.x = f2tf32(av[it].x); u.y = f2tf32(av[it].y);
                u.z = f2tf32(av[it].z); u.w = f2tf32(av[it].w);
                *(uint4*)&asn[m * PA_STRIDE + k4] = u;
                const int kk = lin >> 5;
                const int n4 = (lin & 31) << 2;
                uint4 uw;
                uw.x = f2tf32(bv[it].x); uw.y = f2tf32(bv[it].y);
                uw.z = f2tf32(bv[it].z); uw.w = f2tf32(bv[it].w);
                *(uint4*)&bsn[kk * PB_STRIDE + n4] = uw;
            }
        }
        __syncthreads();
        cur ^= 1;
    }
}

__device__ __forceinline__ void proj_epilogue(
    float* __restrict__ C, const float* __restrict__ bias,
    int m0, int n0, float acc[4][4][4])
{
    const int lane = threadIdx.x & 31, wid = threadIdx.x >> 5;
    const int warp_m = (wid & 1) * 64, warp_n = (wid >> 1) * 32;
    const int g = lane >> 2, t4 = lane & 3;
#pragma unroll
    for (int i = 0; i < 4; i++) {
        const int mrow = m0 + warp_m + i * 16 + g;
#pragma unroll
        for (int j = 0; j < 4; j++) {
            const int n = n0 + warp_n + j * 8 + 2 * t4;
            const float b0 = bias[n], b1 = bias[n + 1];
            *(float2*)(C + (size_t)mrow * DM_ + n) =
                make_float2(acc[i][j][0] + b0, acc[i][j][1] + b1);
            *(float2*)(C + (size_t)(mrow + 8) * DM_ + n) =
                make_float2(acc[i][j][2] + b0, acc[i][j][3] + b1);
        }
    }
}

__global__ __launch_bounds__(256) void qkv_proj_kernel(
    const float* __restrict__ q,  const float* __restrict__ k,  const float* __restrict__ v,
    const float* __restrict__ Wq, const float* __restrict__ Wk, const float* __restrict__ Wv,
    const float* __restrict__ bq, const float* __restrict__ bk, const float* __restrict__ bv)
{
    extern __shared__ uint32_t sm[];
    const float* A; const float* W; const float* bias; float* C;
    if (blockIdx.z == 0)      { A = q; W = Wq; bias = bq; C = g_Qp; }
    else if (blockIdx.z == 1) { A = k; W = Wk; bias = bk; C = g_Kp; }
    else                      { A = v; W = Wv; bias = bv; C = g_Vp; }

    const int m0 = blockIdx.y * 128;
    const int n0 = blockIdx.x * 128;

    float acc[4][4][4];
#pragma unroll
    for (int i = 0; i < 4; i++)
#pragma unroll
        for (int j = 0; j < 4; j++)
#pragma unroll
            for (int r = 0; r < 4; r++) acc[i][j][r] = 0.f;

    proj_gemm_v2(A, W, m0, n0, sm, acc);
    proj_epilogue(C, bias, m0, n0, acc);
}

__global__ __launch_bounds__(256) void out_proj_kernel(
    const float* __restrict__ Wo, const float* __restrict__ bo, float* __restrict__ out)
{
    extern __shared__ uint32_t sm[];
    const int m0 = blockIdx.y * 128;
    const int n0 = blockIdx.x * 128;

    float acc[4][4][4];
#pragma unroll
    for (int i = 0; i < 4; i++)
#pragma unroll
        for (int j = 0; j < 4; j++)
#pragma unroll
            for (int r = 0; r < 4; r++) acc[i][j][r] = 0.f;

    proj_gemm_v2(g_ctx, Wo, m0, n0, sm, acc);
    proj_epilogue(out, bo, m0, n0, acc);
}

// ===========================================================================
// Fused attention (unchanged from R16, proven): per CTA = one (b,h) x 128 q.
// ===========================================================================
#define QS_STRIDE 68
#define KS_STRIDE 68
#define VS_STRIDE 68
#define PS_STRIDE 68

__global__ __launch_bounds__(256) void fused_attn_kernel(float* __restrict__ attn) {
    extern __shared__ uint32_t sm[];
    uint32_t* Qs   = sm;
    uint32_t* Ks   = Qs + 128 * QS_STRIDE;
    uint32_t* Vs   = Ks + 64 * KS_STRIDE;
    float*    Ps   = (float*)(Vs + 64 * VS_STRIDE);
    float*    partM = Ps + 128 * PS_STRIDE;
    float*    partS = partM + 256;
    float*    rowM  = partS + 256;
    float*    rowI  = rowM + 128;

    const int t    = threadIdx.x;
    const int lane = t & 31;
    const int wid  = t >> 5;
    const int warp_m = (wid & 3) * 32;
    const int warp_n = (wid >> 2) * 32;
    const int wn   = wid >> 2;
    const int g  = lane >> 2;
    const int t4 = lane & 3;

    const int m0 = blockIdx.x * 128;
    const int z  = blockIdx.y;
    const int b  = z >> 4, h = z & 15;

    const float* Qp = g_Qp + (size_t)b * S_ * DM_ + h * DK_;
    const float* Kp = g_Kp + (size_t)b * S_ * DM_ + h * DK_;
    const float* Vp = g_Vp + (size_t)b * S_ * DM_ + h * DK_;
    float* attnz    = attn  + (size_t)z * S_ * S_;
    float* Cc       = g_ctx + (size_t)b * S_ * DM_ + h * DK_;

#pragma unroll
    for (int it = 0; it < 8; it++) {
        const int idx = t + it * 256;
        const int r  = idx >> 4;
        const int c4 = (idx & 15) << 2;
        const float4 v = *(const float4*)(Qp + (size_t)(m0 + r) * DM_ + c4);
        uint4 u;
        u.x = f2tf32(v.x); u.y = f2tf32(v.y);
        u.z = f2tf32(v.z); u.w = f2tf32(v.w);
        *(uint4*)&Qs[r * QS_STRIDE + c4] = u;
    }
    __syncthreads();

    float mloc[4], sloc[4];
#pragma unroll
    for (int s = 0; s < 4; s++) { mloc[s] = -INFINITY; sloc[s] = 0.f; }

    // ======================= PASS A: stats =======================
    for (int n0 = 0; n0 < S_; n0 += 64) {
#pragma unroll
        for (int it = 0; it < 4; it++) {
            const int idx = t + it * 256;
            const int n  = idx >> 4;
            const int c4 = (idx & 15) << 2;
            const float4 v = *(const float4*)(Kp + (size_t)(n0 + n) * DM_ + c4);
            uint4 u;
            u.x = f2tf32(v.x); u.y = f2tf32(v.y);
            u.z = f2tf32(v.z); u.w = f2tf32(v.w);
            *(uint4*)&Ks[n * KS_STRIDE + c4] = u;
        }
        __syncthreads();

        float acc[2][4][4];
#pragma unroll
        for (int i = 0; i < 2; i++)
#pragma unroll
            for (int j = 0; j < 4; j++)
#pragma unroll
                for (int r = 0; r < 4; r++) acc[i][j][r] = 0.f;

#pragma unroll
        for (int ks = 0; ks < 64; ks += 8) {
            uint32_t a[2][4], bb[4][2];
#pragma unroll
            for (int i = 0; i < 2; i++) {
                const int r = warp_m + i * 16;
                a[i][0] = Qs[(r + g)     * QS_STRIDE + ks + t4];
                a[i][1] = Qs[(r + g + 8) * QS_STRIDE + ks + t4];
                a[i][2] = Qs[(r + g)     * QS_STRIDE + ks + t4 + 4];
                a[i][3] = Qs[(r + g + 8) * QS_STRIDE + ks + t4 + 4];
            }
#pragma unroll
            for (int j = 0; j < 4; j++) {
                const int c = warp_n + j * 8 + g;
                bb[j][0] = Ks[c * KS_STRIDE + ks + t4];
                bb[j][1] = Ks[c * KS_STRIDE + ks + t4 + 4];
            }
#pragma unroll
            for (int i = 0; i < 2; i++)
#pragma unroll
                for (int j = 0; j < 4; j++)
                    mma_tf32(acc[i][j][0], acc[i][j][1], acc[i][j][2], acc[i][j][3],
                             a[i][0], a[i][1], a[i][2], a[i][3],
                             bb[j][0], bb[j][1]);
        }
        __syncthreads();

#pragma unroll
        for (int i = 0; i < 2; i++) {
#pragma unroll
            for (int half = 0; half < 2; half++) {
                const int slot = i * 2 + half;
                float vals[8];
                float tm = -INFINITY;
#pragma unroll
                for (int j = 0; j < 4; j++) {
                    vals[2 * j]     = acc[i][j][half * 2]     * 0.125f;
                    vals[2 * j + 1] = acc[i][j][half * 2 + 1] * 0.125f;
                    tm = fmaxf(tm, fmaxf(vals[2 * j], vals[2 * j + 1]));
                }
                const float mnew = fmaxf(mloc[slot], tm);
                float ssum = 0.f;
#pragma unroll
                for (int e = 0; e < 8; e++) ssum += __expf(vals[e] - mnew);
                sloc[slot] = sloc[slot] * __expf(mloc[slot] - mnew) + ssum;
                mloc[slot] = mnew;
            }
        }
    }

#pragma unroll
    for (int s = 0; s < 4; s++) {
#pragma unroll
        for (int off = 1; off <= 2; off <<= 1) {
            const float mo = __shfl_xor_sync(0xFFFFFFFFu, mloc[s], off);
            const float so = __shfl_xor_sync(0xFFFFFFFFu, sloc[s], off);
            const float M = fmaxf(mloc[s], mo);
            sloc[s] = sloc[s] * __expf(mloc[s] - M) + so * __expf(mo - M);
            mloc[s] = M;
        }
    }
    if (t4 == 0) {
        const int rows[4] = { warp_m + g, warp_m + 8 + g, warp_m + 16 + g, warp_m + 24 + g };
#pragma unroll
        for (int s = 0; s < 4; s++) {
            partM[wn * 128 + rows[s]] = mloc[s];
            partS[wn * 128 + rows[s]] = sloc[s];
        }
    }
    __syncthreads();
    if (t < 128) {
        const float m0_ = partM[t], m1_ = partM[128 + t];
        const float s0_ = partS[t], s1_ = partS[128 + t];
        const float M = fmaxf(m0_, m1_);
        const float Z = s0_ * __expf(m0_ - M) + s1_ * __expf(m1_ - M);
        rowM[t] = M;
        rowI[t] = 1.0f / Z;
    }
    __syncthreads();

    float fM[4], fI[4];
    {
        const int rows[4] = { warp_m + g, warp_m + 8 + g, warp_m + 16 + g, warp_m + 24 + g };
#pragma unroll
        for (int s = 0; s < 4; s++) { fM[s] = rowM[rows[s]]; fI[s] = rowI[rows[s]]; }
    }

    float cacc[2][4][4];
#pragma unroll
    for (int i = 0; i < 2; i++)
#pragma unroll
        for (int j = 0; j < 4; j++)
#pragma unroll
            for (int r = 0; r < 4; r++) cacc[i][j][r] = 0.f;

    // ======================= PASS B: P write + ctx =======================
    for (int n0 = 0; n0 < S_; n0 += 64) {
#pragma unroll
        for (int it = 0; it < 4; it++) {
            const int idx = t + it * 256;
            const int n  = idx >> 4;
            const int c4 = (idx & 15) << 2;
            const float4 v = *(const float4*)(Kp + (size_t)(n0 + n) * DM_ + c4);
            uint4 u;
            u.x = f2tf32(v.x); u.y = f2tf32(v.y);
            u.z = f2tf32(v.z); u.w = f2tf32(v.w);
            *(uint4*)&Ks[n * KS_STRIDE + c4] = u;
        }
#pragma unroll
        for (int it = 0; it < 4; it++) {
            const int idx = t + it * 256;
            const int kk = idx & 63;
            const int d4 = (idx >> 6) << 2;
            const float4 v = *(const float4*)(Vp + (size_t)(n0 + kk) * DM_ + d4);
            Vs[(d4 + 0) * VS_STRIDE + kk] = f2tf32(v.x);
            Vs[(d4 + 1) * VS_STRIDE + kk] = f2tf32(v.y);
            Vs[(d4 + 2) * VS_STRIDE + kk] = f2tf32(v.z);
            Vs[(d4 + 3) * VS_STRIDE + kk] = f2tf32(v.w);
        }
        __syncthreads();

        float acc[2][4][4];
#pragma unroll
        for (int i = 0; i < 2; i++)
#pragma unroll
            for (int j = 0; j < 4; j++)
#pragma unroll
                for (int r = 0; r < 4; r++) acc[i][j][r] = 0.f;

#pragma unroll
        for (int ks = 0; ks < 64; ks += 8) {
            uint32_t a[2][4], bb[4][2];
#pragma unroll
            for (int i = 0; i < 2; i++) {
                const int r = warp_m + i * 16;
                a[i][0] = Qs[(r + g)     * QS_STRIDE + ks + t4];
                a[i][1] = Qs[(r + g + 8) * QS_STRIDE + ks + t4];
                a[i][2] = Qs[(r + g)     * QS_STRIDE + ks + t4 + 4];
                a[i][3] = Qs[(r + g + 8) * QS_STRIDE + ks + t4 + 4];
            }
#pragma unroll
            for (int j = 0; j < 4; j++) {
                const int c = warp_n + j * 8 + g;
                bb[j][0] = Ks[c * KS_STRIDE + ks + t4];
                bb[j][1] = Ks[c * KS_STRIDE + ks + t4 + 4];
            }
#pragma unroll
            for (int i = 0; i < 2; i++)
#pragma unroll
                for (int j = 0; j < 4; j++)
                    mma_tf32(acc[i][j][0], acc[i][j][1], acc[i][j][2], acc[i][j][3],
                             a[i][0], a[i][1], a[i][2], a[i][3],
                             bb[j][0], bb[j][1]);
        }

#pragma unroll
        for (int i = 0; i < 2; i++) {
            const int r0 = warp_m + i * 16 + g;
            const int r1 = r0 + 8;
            const int s0_ = i * 2, s1_ = i * 2 + 1;
#pragma unroll
            for (int j = 0; j < 4; j++) {
                const int col = warp_n + j * 8 + 2 * t4;
                const float p00 = __expf(acc[i][j][0] * 0.125f - fM[s0_]) * fI[s0_];
                const float p01 = __expf(acc[i][j][1] * 0.125f - fM[s0_]) * fI[s0_];
                const float p10 = __expf(acc[i][j][2] * 0.125f - fM[s1_]) * fI[s1_];
                const float p11 = __expf(acc[i][j][3] * 0.125f - fM[s1_]) * fI[s1_];
                *(float2*)&Ps[r0 * PS_STRIDE + col] = make_float2(p00, p01);
                *(float2*)&Ps[r1 * PS_STRIDE + col] = make_float2(p10, p11);
            }
        }
        __syncthreads();

#pragma unroll
        for (int it = 0; it < 8; it++) {
            const int idx = t + it * 256;
            const int r  = idx >> 4;
            const int c4 = (idx & 15) << 2;
            *(float4*)(attnz + (size_t)(m0 + r) * S_ + n0 + c4) =
                *(float4*)&Ps[r * PS_STRIDE + c4];
        }

#pragma unroll
        for (int ks = 0; ks < 64; ks += 8) {
            uint32_t a[2][4], bb[4][2];
#pragma unroll
            for (int i = 0; i < 2; i++) {
                const int r = warp_m + i * 16;
                a[i][0] = f2tf32(Ps[(r + g)     * PS_STRIDE + ks + t4]);
                a[i][1] = f2tf32(Ps[(r + g + 8) * PS_STRIDE + ks + t4]);
                a[i][2] = f2tf32(Ps[(r + g)     * PS_STRIDE + ks + t4 + 4]);
                a[i][3] = f2tf32(Ps[(r + g + 8) * PS_STRIDE + ks + t4 + 4]);
            }
#pragma unroll
            for (int j = 0; j < 4; j++) {
                const int c = warp_n + j * 8 + g;
                bb[j][0] = Vs[c * VS_STRIDE + ks + t4];
                bb[j][1] = Vs[c * VS_STRIDE + ks + t4 + 4];
            }
#pragma unroll
            for (int i = 0; i < 2; i++)
#pragma unroll
                for (int j = 0; j < 4; j++)
                    mma_tf32(cacc[i][j][0], cacc[i][j][1], cacc[i][j][2], cacc[i][j][3],
                             a[i][0], a[i][1], a[i][2], a[i][3],
                             bb[j][0], bb[j][1]);
        }
        __syncthreads();
    }

#pragma unroll
    for (int i = 0; i < 2; i++) {
        const int mrow = m0 + warp_m + i * 16 + g;
#pragma unroll
        for (int j = 0; j < 4; j++) {
            const int n = warp_n + j * 8 + 2 * t4;
            *(float2*)(Cc + (size_t)mrow * DM_ + n) =
                make_float2(cacc[i][j][0], cacc[i][j][1]);
            *(float2*)(Cc + (size_t)(mrow + 8) * DM_ + n) =
                make_float2(cacc[i][j][2], cacc[i][j][3]);
        }
    }
}

#define FUSED_SMEM ((128*QS_STRIDE + 64*KS_STRIDE + 64*VS_STRIDE + 128*PS_STRIDE + 256 + 256 + 128 + 128) * 4)

// ---------------------------------------------------------------------------
// Launch. Inputs: signature order. Outputs: output first, then attn.
// ---------------------------------------------------------------------------
extern "C" void kernel_launch(void* const* d_in, const int* in_sizes, int n_in,
                              void* d_out, int out_size) {
    const float* q  = (const float*)d_in[0];
    const float* k  = (const float*)d_in[1];
    const float* v  = (const float*)d_in[2];
    const float* Wq = (const float*)d_in[3];
    const float* bq = (const float*)d_in[4];
    const float* Wk = (const float*)d_in[5];
    const float* bk = (const float*)d_in[6];
    const float* Wv = (const float*)d_in[7];
    const float* bv = (const float*)d_in[8];
    const float* Wo = (const float*)d_in[9];
    const float* bo = (const float*)d_in[10];

    float* out;
    float* attn;
    if (out_size == N_ACT) {
        float* sa; cudaGetSymbolAddress((void**)&sa, g_attn_scratch);
        out = (float*)d_out; attn = sa;
    } else if (out_size == N_ATTN) {
        float* so; cudaGetSymbolAddress((void**)&so, g_out_scratch);
        attn = (float*)d_out; out = so;
    } else {
        out  = (float*)d_out;
        attn = (float*)d_out + N_ACT;
    }

    static bool attr_set = false;
    if (!attr_set) {
        cudaFuncSetAttribute(fused_attn_kernel,
                             cudaFuncAttributeMaxDynamicSharedMemorySize, FUSED_SMEM);
        cudaFuncSetAttribute(qkv_proj_kernel,
                             cudaFuncAttributeMaxDynamicSharedMemorySize, PROJ_SMEM);
        cudaFuncSetAttribute(out_proj_kernel,
                             cudaFuncAttributeMaxDynamicSharedMemorySize, PROJ_SMEM);
        attr_set = true;
    }

    dim3 blk(256);

    dim3 gqkv(DM_ / 128, BS_TOK / 128, 3);           // (8, 32, 3)
    qkv_proj_kernel<<<gqkv, blk, PROJ_SMEM>>>(q, k, v, Wq, Wk, Wv, bq, bk, bv);

    dim3 gf(S_ / 128, NBH);                          // (16, 32)
    fused_attn_kernel<<<gf, blk, FUSED_SMEM>>>(attn);

    dim3 gout(DM_ / 128, BS_TOK / 128);              // (8, 32)
    out_proj_kernel<<<gout, blk, PROJ_SMEM>>>(Wo, bo, out);
}